// round 3
// baseline (speedup 1.0000x reference)
#include <cuda_runtime.h>
#include <cuda_bf16.h>
#include <mma.h>
#include <cstdint>

using namespace nvcuda;

static constexpr int BATCH = 4;
static constexpr int NTOK  = 4096;   // H*W
static constexpr int CH    = 512;
static constexpr int FGD   = 64;

static constexpr long long O_ELEMS = (long long)BATCH * NTOK * CH;    // 8388608
static constexpr long long B_ELEMS = (long long)BATCH * NTOK * NTOK;  // 67108864

// ---------------- scratch (static __device__ -- no allocations allowed) ----------
__device__ float d_f[(size_t)BATCH * NTOK * FGD];
__device__ float d_g[(size_t)BATCH * NTOK * FGD];
__device__ float d_h[(size_t)BATCH * NTOK * CH];
__device__ float d_oatt[(size_t)BATCH * NTOK * CH];
__device__ float d_rowm[BATCH * NTOK];
__device__ float d_rowl[BATCH * NTOK];
__device__ float d_beta_scratch[(size_t)BATCH * NTOK * NTOK]; // only if harness wants o-only

// ---------------- bf16 split helpers (x = hi + lo, ~17-bit effective mantissa) ---
__device__ __forceinline__ void split4(const float4 v, __nv_bfloat16* hi, __nv_bfloat16* lo) {
    hi[0] = __float2bfloat16(v.x); lo[0] = __float2bfloat16(v.x - __bfloat162float(hi[0]));
    hi[1] = __float2bfloat16(v.y); lo[1] = __float2bfloat16(v.y - __bfloat162float(hi[1]));
    hi[2] = __float2bfloat16(v.z); lo[2] = __float2bfloat16(v.z - __bfloat162float(hi[2]));
    hi[3] = __float2bfloat16(v.w); lo[3] = __float2bfloat16(v.w - __bfloat162float(hi[3]));
}

// ================================================================================
// Big-tile GEMM: C[M,N] = act(A[M,K] @ B[K,N] + bias), all fp32 row-major.
// CTA tile 128x128, KC=32, 8 warps (4x2), warp tile 32x64 = acc[2][4].
// bf16 3-term split (hi*hi + hi*lo + lo*hi). Double-buffered smem, register
// prefetch pipeline, single __syncthreads per k-chunk.
// Requirements: M%128==0, N%128==0, K%32==0.
// ================================================================================
static constexpr int G2_ALD  = 40;    // A smem ld (bf16): 32 + 8 skew
static constexpr int G2_BLD  = 136;   // B smem ld (bf16): 128 + 8 skew
static constexpr int G2_ABUF = 128 * G2_ALD * 2;  // bytes per A half (hi or lo) = 10240
static constexpr int G2_BBUF = 32 * G2_BLD * 2;   // bytes per B half = 8704
static constexpr int G2_STAGE = 2 * (G2_ABUF + G2_BBUF);  // one buffer = 37888
static constexpr int G2_SMEM  = 2 * G2_STAGE;             // 75776 (also >= 128*132*4 epilogue)
static constexpr int G2_CLD   = 132;

__global__ void __launch_bounds__(256)
gemm128_kernel(const float* __restrict__ A, const float* __restrict__ B,
               const float* __restrict__ bias, float* __restrict__ C,
               int K, int N, long long sA, long long sB, long long sC, int relu)
{
    extern __shared__ __align__(16) unsigned char smdyn[];
    float* Csm = reinterpret_cast<float*>(smdyn);

    A += (long long)blockIdx.z * sA;
    B += (long long)blockIdx.z * sB;
    C += (long long)blockIdx.z * sC;
    const int m0  = blockIdx.y * 128;
    const int n0  = blockIdx.x * 128;
    const int tid = threadIdx.x;
    const int wid = tid >> 5;
    const int wm  = wid >> 1;   // 0..3  -> rows 32*wm
    const int wn  = wid & 1;    // 0..1  -> cols 64*wn

    // per-thread staging coordinates
    const int arow = tid >> 3;              // approach A: 4 f4/thread, rows 0..127 per i-step? (recomputed below)
    (void)arow;

    wmma::fragment<wmma::accumulator, 16, 16, 16, float> acc[2][4];
    #pragma unroll
    for (int i = 0; i < 2; i++)
        #pragma unroll
        for (int j = 0; j < 4; j++)
            wmma::fill_fragment(acc[i][j], 0.0f);

    const int NCHUNK = K >> 5;
    float4 ra[4], rb[4];

    // prefetch chunk 0 into registers
    #pragma unroll
    for (int i = 0; i < 4; i++) {
        int idx = tid + i * 256;
        int row = idx >> 3;                 // 0..127
        int c4  = (idx & 7) << 2;           // 0..28
        ra[i] = *reinterpret_cast<const float4*>(A + (long long)(m0 + row) * K + c4);
    }
    #pragma unroll
    for (int i = 0; i < 4; i++) {
        int idx  = tid + i * 256;
        int krow = idx >> 5;                // 0..31
        int c4   = (idx & 31) << 2;         // 0..124
        rb[i] = *reinterpret_cast<const float4*>(B + (long long)krow * N + n0 + c4);
    }

    #pragma unroll 1
    for (int c = 0; c < NCHUNK; c++) {
        unsigned char* buf = smdyn + (c & 1) * G2_STAGE;
        __nv_bfloat16* Ahi = reinterpret_cast<__nv_bfloat16*>(buf);
        __nv_bfloat16* Alo = Ahi + 128 * G2_ALD;
        __nv_bfloat16* Bhi = Alo + 128 * G2_ALD;
        __nv_bfloat16* Blo = Bhi + 32 * G2_BLD;

        // store prefetched registers (split to hi/lo)
        #pragma unroll
        for (int i = 0; i < 4; i++) {
            int idx = tid + i * 256;
            int row = idx >> 3;
            int c4  = (idx & 7) << 2;
            split4(ra[i], &Ahi[row * G2_ALD + c4], &Alo[row * G2_ALD + c4]);
        }
        #pragma unroll
        for (int i = 0; i < 4; i++) {
            int idx  = tid + i * 256;
            int krow = idx >> 5;
            int c4   = (idx & 31) << 2;
            split4(rb[i], &Bhi[krow * G2_BLD + c4], &Blo[krow * G2_BLD + c4]);
        }
        __syncthreads();

        // issue next chunk's global loads (latency hidden under the mma block)
        if (c + 1 < NCHUNK) {
            const long long k0 = (long long)(c + 1) << 5;
            #pragma unroll
            for (int i = 0; i < 4; i++) {
                int idx = tid + i * 256;
                int row = idx >> 3;
                int c4  = (idx & 7) << 2;
                ra[i] = *reinterpret_cast<const float4*>(A + (long long)(m0 + row) * K + k0 + c4);
            }
            #pragma unroll
            for (int i = 0; i < 4; i++) {
                int idx  = tid + i * 256;
                int krow = idx >> 5;
                int c4   = (idx & 31) << 2;
                rb[i] = *reinterpret_cast<const float4*>(B + (k0 + krow) * N + n0 + c4);
            }
        }

        #pragma unroll
        for (int ks = 0; ks < 2; ks++) {
            wmma::fragment<wmma::matrix_a, 16, 16, 16, __nv_bfloat16, wmma::row_major> ah[2], al[2];
            #pragma unroll
            for (int i = 0; i < 2; i++) {
                wmma::load_matrix_sync(ah[i], &Ahi[(wm * 32 + i * 16) * G2_ALD + ks * 16], G2_ALD);
                wmma::load_matrix_sync(al[i], &Alo[(wm * 32 + i * 16) * G2_ALD + ks * 16], G2_ALD);
            }
            #pragma unroll
            for (int j = 0; j < 4; j++) {
                wmma::fragment<wmma::matrix_b, 16, 16, 16, __nv_bfloat16, wmma::row_major> bh, bl;
                wmma::load_matrix_sync(bh, &Bhi[(ks * 16) * G2_BLD + wn * 64 + j * 16], G2_BLD);
                wmma::load_matrix_sync(bl, &Blo[(ks * 16) * G2_BLD + wn * 64 + j * 16], G2_BLD);
                #pragma unroll
                for (int i = 0; i < 2; i++) {
                    wmma::mma_sync(acc[i][j], ah[i], bh, acc[i][j]);
                    wmma::mma_sync(acc[i][j], ah[i], bl, acc[i][j]);
                    wmma::mma_sync(acc[i][j], al[i], bh, acc[i][j]);
                }
            }
        }
        // next iteration writes the other buffer; the syncthreads above (next iter)
        // orders those stores after every warp's mma on that buffer. single-sync safe.
    }

    // epilogue: smem roundtrip (Csm aliases the staging buffers)
    __syncthreads();
    #pragma unroll
    for (int i = 0; i < 2; i++)
        #pragma unroll
        for (int j = 0; j < 4; j++)
            wmma::store_matrix_sync(&Csm[(wm * 32 + i * 16) * G2_CLD + wn * 64 + j * 16],
                                    acc[i][j], G2_CLD, wmma::mem_row_major);
    __syncthreads();

    #pragma unroll
    for (int i = 0; i < 16; i++) {
        int idx = tid + i * 256;
        int row = idx >> 5;                 // 0..127
        int c4  = (idx & 31) << 2;          // 0..124
        float4 v = *reinterpret_cast<const float4*>(&Csm[row * G2_CLD + c4]);
        if (bias != nullptr) {
            float4 bv = *reinterpret_cast<const float4*>(bias + n0 + c4);
            v.x += bv.x; v.y += bv.y; v.z += bv.z; v.w += bv.w;
        }
        if (relu) {
            v.x = fmaxf(v.x, 0.f); v.y = fmaxf(v.y, 0.f);
            v.z = fmaxf(v.z, 0.f); v.w = fmaxf(v.w, 0.f);
        }
        *reinterpret_cast<float4*>(C + (long long)(m0 + row) * N + n0 + c4) = v;
    }
}

// ================== small GEMM (N=64): C = act(A[M,512] @ B[512,64] + bias) ======
static constexpr int GBM = 128, GBN = 64, GBK = 32;
static constexpr int ALD = GBK + 8;   // 40
static constexpr int BLD = GBN + 8;   // 72
static constexpr int CLD = GBN + 4;   // 68
static constexpr int GEMM_SMEM_BYTES = 35840;

__global__ void __launch_bounds__(256)
gemm_split_kernel(const float* __restrict__ A, const float* __restrict__ B,
                  const float* __restrict__ bias, float* __restrict__ C,
                  int K, int N, int relu)
{
    __shared__ __align__(16) unsigned char smbuf[GEMM_SMEM_BYTES];
    __nv_bfloat16* Ahi = reinterpret_cast<__nv_bfloat16*>(smbuf);
    __nv_bfloat16* Alo = Ahi + GBM * ALD;
    __nv_bfloat16* Bhi = Alo + GBM * ALD;
    __nv_bfloat16* Blo = Bhi + GBK * BLD;
    float*         Csm = reinterpret_cast<float*>(smbuf);

    const int m0  = blockIdx.y * GBM;
    const int n0  = blockIdx.x * GBN;
    const int tid = threadIdx.x;
    const int wid = tid >> 5;
    const int wm  = wid >> 1;
    const int wn  = wid & 1;

    wmma::fragment<wmma::accumulator, 16, 16, 16, float> acc[2][2];
    #pragma unroll
    for (int i = 0; i < 2; i++)
        #pragma unroll
        for (int j = 0; j < 2; j++)
            wmma::fill_fragment(acc[i][j], 0.0f);

    for (int kt = 0; kt < K; kt += GBK) {
        #pragma unroll
        for (int i = 0; i < 4; i++) {
            int idx = tid + i * 256;
            int row = idx >> 3;
            int c4  = (idx & 7) << 2;
            float4 v = *reinterpret_cast<const float4*>(A + (long long)(m0 + row) * K + kt + c4);
            split4(v, &Ahi[row * ALD + c4], &Alo[row * ALD + c4]);
        }
        #pragma unroll
        for (int i = 0; i < 2; i++) {
            int idx = tid + i * 256;
            int row = idx >> 4;
            int c4  = (idx & 15) << 2;
            float4 v = *reinterpret_cast<const float4*>(B + (long long)(kt + row) * N + n0 + c4);
            split4(v, &Bhi[row * BLD + c4], &Blo[row * BLD + c4]);
        }
        __syncthreads();
        #pragma unroll
        for (int ks = 0; ks < 2; ks++) {
            wmma::fragment<wmma::matrix_a, 16, 16, 16, __nv_bfloat16, wmma::row_major> ah[2], al[2];
            wmma::fragment<wmma::matrix_b, 16, 16, 16, __nv_bfloat16, wmma::row_major> bh[2], bl[2];
            #pragma unroll
            for (int r2 = 0; r2 < 2; r2++) {
                wmma::load_matrix_sync(ah[r2], &Ahi[(wm * 32 + r2 * 16) * ALD + ks * 16], ALD);
                wmma::load_matrix_sync(al[r2], &Alo[(wm * 32 + r2 * 16) * ALD + ks * 16], ALD);
            }
            #pragma unroll
            for (int cn = 0; cn < 2; cn++) {
                wmma::load_matrix_sync(bh[cn], &Bhi[(ks * 16) * BLD + wn * 32 + cn * 16], BLD);
                wmma::load_matrix_sync(bl[cn], &Blo[(ks * 16) * BLD + wn * 32 + cn * 16], BLD);
            }
            #pragma unroll
            for (int r2 = 0; r2 < 2; r2++)
                #pragma unroll
                for (int cn = 0; cn < 2; cn++) {
                    wmma::mma_sync(acc[r2][cn], ah[r2], bh[cn], acc[r2][cn]);
                    wmma::mma_sync(acc[r2][cn], ah[r2], bl[cn], acc[r2][cn]);
                    wmma::mma_sync(acc[r2][cn], al[r2], bh[cn], acc[r2][cn]);
                }
        }
        __syncthreads();
    }

    #pragma unroll
    for (int r2 = 0; r2 < 2; r2++)
        #pragma unroll
        for (int cn = 0; cn < 2; cn++)
            wmma::store_matrix_sync(&Csm[(wm * 32 + r2 * 16) * CLD + wn * 32 + cn * 16],
                                    acc[r2][cn], CLD, wmma::mem_row_major);
    __syncthreads();

    #pragma unroll
    for (int i = 0; i < 8; i++) {
        int idx = tid + i * 256;
        int row = idx >> 4;
        int c4  = (idx & 15) << 2;
        float4 v = *reinterpret_cast<const float4*>(&Csm[row * CLD + c4]);
        if (bias != nullptr) {
            float4 bv = *reinterpret_cast<const float4*>(bias + n0 + c4);
            v.x += bv.x; v.y += bv.y; v.z += bv.z; v.w += bv.w;
        }
        if (relu) {
            v.x = fmaxf(v.x, 0.f); v.y = fmaxf(v.y, 0.f);
            v.z = fmaxf(v.z, 0.f); v.w = fmaxf(v.w, 0.f);
        }
        *reinterpret_cast<float4*>(C + (long long)(m0 + row) * N + n0 + c4) = v;
    }
}

// ================== scores: raw S = g @ f^T streamed out + online row max/sum ====
static constexpr int SLD = 132;
static constexpr int GLD = 72;
static constexpr int SCORES_SMEM = 4 * 128 * GLD * 2 + 128 * SLD * 4; // 141312 B

__global__ void __launch_bounds__(512)
scores_kernel(const float* __restrict__ g, const float* __restrict__ f,
              float* __restrict__ sraw, float* __restrict__ rowm, float* __restrict__ rowl)
{
    extern __shared__ unsigned char smraw[];
    __nv_bfloat16* Ghi = reinterpret_cast<__nv_bfloat16*>(smraw);
    __nv_bfloat16* Glo = Ghi + 128 * GLD;
    __nv_bfloat16* Fhi = Glo + 128 * GLD;
    __nv_bfloat16* Flo = Fhi + 128 * GLD;
    float*         S   = reinterpret_cast<float*>(Flo + 128 * GLD);

    const int b   = blockIdx.y;
    const int r0  = blockIdx.x * 128;
    const int tid = threadIdx.x;
    const int wid = tid >> 5;
    const int wm  = wid >> 2;
    const int wn  = wid & 3;

    const float* gbase = g + ((long long)b * NTOK + r0) * FGD;
    const float* fbase = f + (long long)b * NTOK * FGD;

    #pragma unroll
    for (int i = 0; i < 4; i++) {
        int idx = tid + i * 512;
        int row = idx >> 4;
        int c4  = (idx & 15) << 2;
        float4 v = *reinterpret_cast<const float4*>(gbase + row * FGD + c4);
        split4(v, &Ghi[row * GLD + c4], &Glo[row * GLD + c4]);
    }

    float m_run = -1e30f, l_run = 0.0f;
    const int srow = tid >> 2;
    const int q    = tid & 3;
    const float* Sscan = &S[srow * SLD + q * 32];

    for (int ci = 0; ci < 32; ci++) {
        __syncthreads();
        #pragma unroll
        for (int i = 0; i < 4; i++) {
            int idx = tid + i * 512;
            int row = idx >> 4;
            int c4  = (idx & 15) << 2;
            float4 v = *reinterpret_cast<const float4*>(fbase + (long long)(ci * 128 + row) * FGD + c4);
            split4(v, &Fhi[row * GLD + c4], &Flo[row * GLD + c4]);
        }
        __syncthreads();

        wmma::fragment<wmma::accumulator, 16, 16, 16, float> acc[2][2];
        #pragma unroll
        for (int i = 0; i < 2; i++)
            #pragma unroll
            for (int j = 0; j < 2; j++)
                wmma::fill_fragment(acc[i][j], 0.0f);

        #pragma unroll
        for (int ks = 0; ks < 4; ks++) {
            wmma::fragment<wmma::matrix_a, 16, 16, 16, __nv_bfloat16, wmma::row_major> ah[2], al[2];
            wmma::fragment<wmma::matrix_b, 16, 16, 16, __nv_bfloat16, wmma::col_major> bh[2], bl[2];
            #pragma unroll
            for (int r2 = 0; r2 < 2; r2++) {
                wmma::load_matrix_sync(ah[r2], &Ghi[(wm * 32 + r2 * 16) * GLD + ks * 16], GLD);
                wmma::load_matrix_sync(al[r2], &Glo[(wm * 32 + r2 * 16) * GLD + ks * 16], GLD);
            }
            #pragma unroll
            for (int cn = 0; cn < 2; cn++) {
                wmma::load_matrix_sync(bh[cn], &Fhi[(wn * 32 + cn * 16) * GLD + ks * 16], GLD);
                wmma::load_matrix_sync(bl[cn], &Flo[(wn * 32 + cn * 16) * GLD + ks * 16], GLD);
            }
            #pragma unroll
            for (int r2 = 0; r2 < 2; r2++)
                #pragma unroll
                for (int cn = 0; cn < 2; cn++) {
                    wmma::mma_sync(acc[r2][cn], ah[r2], bh[cn], acc[r2][cn]);
                    wmma::mma_sync(acc[r2][cn], ah[r2], bl[cn], acc[r2][cn]);
                    wmma::mma_sync(acc[r2][cn], al[r2], bh[cn], acc[r2][cn]);
                }
        }
        #pragma unroll
        for (int r2 = 0; r2 < 2; r2++)
            #pragma unroll
            for (int cn = 0; cn < 2; cn++)
                wmma::store_matrix_sync(&S[(wm * 32 + r2 * 16) * SLD + wn * 32 + cn * 16],
                                        acc[r2][cn], SLD, wmma::mem_row_major);
        __syncthreads();

        size_t gout = (size_t)(b * NTOK + r0) * NTOK + (size_t)ci * 128;
        #pragma unroll
        for (int i = 0; i < 8; i++) {
            int idx = tid + i * 512;
            int row = idx >> 5;
            int c4  = (idx & 31) << 2;
            float4 v = *reinterpret_cast<const float4*>(&S[row * SLD + c4]);
            *reinterpret_cast<float4*>(sraw + gout + (size_t)row * NTOK + c4) = v;
        }
        float vmax = -1e30f;
        #pragma unroll
        for (int j = 0; j < 32; j++) vmax = fmaxf(vmax, Sscan[j]);
        float mn = fmaxf(m_run, vmax);
        float add = 0.0f;
        #pragma unroll
        for (int j = 0; j < 32; j++) add += __expf(Sscan[j] - mn);
        l_run = l_run * __expf(m_run - mn) + add;
        m_run = mn;
    }

    #pragma unroll
    for (int off = 1; off < 4; off <<= 1) {
        float mo  = __shfl_xor_sync(0xffffffffu, m_run, off);
        float lo2 = __shfl_xor_sync(0xffffffffu, l_run, off);
        float mn  = fmaxf(m_run, mo);
        l_run = l_run * __expf(m_run - mn) + lo2 * __expf(mo - mn);
        m_run = mn;
    }
    if (q == 0) {
        rowm[b * NTOK + r0 + srow] = m_run;
        rowl[b * NTOK + r0 + srow] = l_run;
    }
}

// ================== normalize: beta = exp(s - m_row) / l_row =====================
__global__ void __launch_bounds__(256)
normalize_kernel(float* __restrict__ beta,
                 const float* __restrict__ rowm, const float* __restrict__ rowl)
{
    long long idx = (long long)blockIdx.x * 256 + threadIdx.x;
    if (idx >= (B_ELEMS >> 2)) return;
    int rowg = (int)(idx >> 10);
    float m   = __ldg(rowm + rowg);
    float inv = 1.0f / __ldg(rowl + rowg);
    float4 v = *reinterpret_cast<float4*>(beta + idx * 4);
    v.x = __expf(v.x - m) * inv;
    v.y = __expf(v.y - m) * inv;
    v.z = __expf(v.z - m) * inv;
    v.w = __expf(v.w - m) * inv;
    *reinterpret_cast<float4*>(beta + idx * 4) = v;
}

// ================== launch ========================================================
extern "C" void kernel_launch(void* const* d_in, const int* in_sizes, int n_in,
                              void* d_out, int out_size)
{
    (void)in_sizes; (void)n_in;
    const float* l  = (const float*)d_in[0];
    const float* r  = (const float*)d_in[1];
    const float* Wf = (const float*)d_in[2];
    const float* Wg = (const float*)d_in[3];
    const float* Wh = (const float*)d_in[4];
    const float* Wo = (const float*)d_in[5];
    const float* bf = (const float*)d_in[6];
    const float* bg = (const float*)d_in[7];
    const float* bh = (const float*)d_in[8];
    const float* bo = (const float*)d_in[9];
    float* out = (float*)d_out;

    float *p_f, *p_g, *p_h, *p_oatt, *p_rowm, *p_rowl, *p_bscr;
    cudaGetSymbolAddress((void**)&p_f,    d_f);
    cudaGetSymbolAddress((void**)&p_g,    d_g);
    cudaGetSymbolAddress((void**)&p_h,    d_h);
    cudaGetSymbolAddress((void**)&p_oatt, d_oatt);
    cudaGetSymbolAddress((void**)&p_rowm, d_rowm);
    cudaGetSymbolAddress((void**)&p_rowl, d_rowl);
    cudaGetSymbolAddress((void**)&p_bscr, d_beta_scratch);

    float* o_out    = nullptr;
    float* beta_out = nullptr;
    long long osz = (long long)out_size;
    if (osz >= O_ELEMS + B_ELEMS) { o_out = out; beta_out = out + O_ELEMS; }
    else if (osz == B_ELEMS)      { beta_out = out; }
    else                          { o_out = out; beta_out = p_bscr; }

    cudaFuncSetAttribute(scores_kernel, cudaFuncAttributeMaxDynamicSharedMemorySize, SCORES_SMEM);
    cudaFuncSetAttribute(gemm128_kernel, cudaFuncAttributeMaxDynamicSharedMemorySize, G2_SMEM);

    // f = relu(l @ Wf + bf)   [16384, 64]
    gemm_split_kernel<<<dim3(1, 128, 1), 256>>>(l, Wf, bf, p_f, 512, 64, 1);
    // g = relu(r @ Wg + bg)   [16384, 64]
    gemm_split_kernel<<<dim3(1, 128, 1), 256>>>(r, Wg, bg, p_g, 512, 64, 1);
    // h = relu(l @ Wh + bh)   [16384, 512]
    gemm128_kernel<<<dim3(4, 128, 1), 256, G2_SMEM>>>(l, Wh, bh, p_h, 512, 512, 0, 0, 0, 1);
    // raw scores + row max / sumexp
    scores_kernel<<<dim3(32, 4, 1), 512, SCORES_SMEM>>>(p_g, p_f, beta_out, p_rowm, p_rowl);
    // beta = softmax(s)
    normalize_kernel<<<65536, 256>>>(beta_out, p_rowm, p_rowl);
    if (o_out) {
        // o_att = beta @ h  (per batch), 128x128 pipelined tiles
        gemm128_kernel<<<dim3(4, 32, 4), 256, G2_SMEM>>>(beta_out, p_h, nullptr, p_oatt,
                                                         4096, 512,
                                                         (long long)NTOK * NTOK,
                                                         (long long)NTOK * CH,
                                                         (long long)NTOK * CH, 0);
        // o = relu(o_att @ Wo + bo)   [16384, 512]
        gemm128_kernel<<<dim3(4, 128, 1), 256, G2_SMEM>>>(p_oatt, Wo, bo, o_out, 512, 512, 0, 0, 0, 1);
    }
}

// round 4
// speedup vs baseline: 1.4088x; 1.4088x over previous
#include <cuda_runtime.h>
#include <cuda_bf16.h>
#include <cuda_fp16.h>
#include <mma.h>
#include <cstdint>

using namespace nvcuda;

static constexpr int BATCH = 4;
static constexpr int NTOK  = 4096;   // H*W
static constexpr int CH    = 512;
static constexpr int FGD   = 64;

static constexpr long long O_ELEMS = (long long)BATCH * NTOK * CH;    // 8388608
static constexpr long long B_ELEMS = (long long)BATCH * NTOK * NTOK;  // 67108864

// ---------------- scratch (static __device__ -- no allocations allowed) ----------
__device__ float d_f[(size_t)BATCH * NTOK * FGD];
__device__ float d_g[(size_t)BATCH * NTOK * FGD];
__device__ float d_h[(size_t)BATCH * NTOK * CH];
__device__ float d_oatt[(size_t)BATCH * NTOK * CH];
__device__ float d_rowm[BATCH * NTOK];
__device__ float d_rowl[BATCH * NTOK];
__device__ float d_beta_scratch[(size_t)BATCH * NTOK * NTOK]; // only if harness wants o-only

// ---------------- bf16 split helper (x = hi + lo, ~17-bit effective mantissa) ----
__device__ __forceinline__ void split4(const float4 v, __nv_bfloat16* hi, __nv_bfloat16* lo) {
    hi[0] = __float2bfloat16(v.x); lo[0] = __float2bfloat16(v.x - __bfloat162float(hi[0]));
    hi[1] = __float2bfloat16(v.y); lo[1] = __float2bfloat16(v.y - __bfloat162float(hi[1]));
    hi[2] = __float2bfloat16(v.z); lo[2] = __float2bfloat16(v.z - __bfloat162float(hi[2]));
    hi[3] = __float2bfloat16(v.w); lo[3] = __float2bfloat16(v.w - __bfloat162float(hi[3]));
}

// ---------------- fp16 split helper (x = hi + lo, ~22-bit effective mantissa) ----
__device__ __forceinline__ void split4h(const float4 v, __half* hi, __half* lo) {
    hi[0] = __float2half_rn(v.x); lo[0] = __float2half_rn(v.x - __half2float(hi[0]));
    hi[1] = __float2half_rn(v.y); lo[1] = __float2half_rn(v.y - __half2float(hi[1]));
    hi[2] = __float2half_rn(v.z); lo[2] = __float2half_rn(v.z - __half2float(hi[2]));
    hi[3] = __float2half_rn(v.w); lo[3] = __float2half_rn(v.w - __half2float(hi[3]));
}
__device__ __forceinline__ void cvt4h(const float4 v, __half* o) {
    o[0] = __float2half_rn(v.x); o[1] = __float2half_rn(v.y);
    o[2] = __float2half_rn(v.z); o[3] = __float2half_rn(v.w);
}

// ================== generic GEMM: C = act(A[M,K] @ B[K,N] + bias) =================
// bf16-split 3-mma scheme (near-fp32 accuracy). M%128==0, N%64==0, K%32==0.
static constexpr int GBM = 128, GBN = 64, GBK = 32;
static constexpr int ALD = GBK + 8;   // 40
static constexpr int BLD = GBN + 8;   // 72
static constexpr int CLD = GBN + 4;   // 68
static constexpr int GEMM_SMEM_BYTES = 35840;

__global__ void __launch_bounds__(256)
gemm_split_kernel(const float* __restrict__ A, const float* __restrict__ B,
                  const float* __restrict__ bias, float* __restrict__ C,
                  int K, int N,
                  long long sA, long long sB, long long sC, int relu)
{
    __shared__ __align__(16) unsigned char smbuf[GEMM_SMEM_BYTES];
    __nv_bfloat16* Ahi = reinterpret_cast<__nv_bfloat16*>(smbuf);
    __nv_bfloat16* Alo = Ahi + GBM * ALD;
    __nv_bfloat16* Bhi = Alo + GBM * ALD;
    __nv_bfloat16* Blo = Bhi + GBK * BLD;
    float*         Csm = reinterpret_cast<float*>(smbuf);

    A += (long long)blockIdx.z * sA;
    B += (long long)blockIdx.z * sB;
    C += (long long)blockIdx.z * sC;
    const int m0  = blockIdx.y * GBM;
    const int n0  = blockIdx.x * GBN;
    const int tid = threadIdx.x;
    const int wid = tid >> 5;
    const int wm  = wid >> 1;  // 0..3
    const int wn  = wid & 1;   // 0..1

    wmma::fragment<wmma::accumulator, 16, 16, 16, float> acc[2][2];
    #pragma unroll
    for (int i = 0; i < 2; i++)
        #pragma unroll
        for (int j = 0; j < 2; j++)
            wmma::fill_fragment(acc[i][j], 0.0f);

    for (int kt = 0; kt < K; kt += GBK) {
        #pragma unroll
        for (int i = 0; i < 4; i++) {
            int idx = tid + i * 256;
            int row = idx >> 3;
            int c4  = (idx & 7) << 2;
            float4 v = *reinterpret_cast<const float4*>(A + (long long)(m0 + row) * K + kt + c4);
            split4(v, &Ahi[row * ALD + c4], &Alo[row * ALD + c4]);
        }
        #pragma unroll
        for (int i = 0; i < 2; i++) {
            int idx = tid + i * 256;
            int row = idx >> 4;
            int c4  = (idx & 15) << 2;
            float4 v = *reinterpret_cast<const float4*>(B + (long long)(kt + row) * N + n0 + c4);
            split4(v, &Bhi[row * BLD + c4], &Blo[row * BLD + c4]);
        }
        __syncthreads();
        #pragma unroll
        for (int ks = 0; ks < 2; ks++) {
            wmma::fragment<wmma::matrix_a, 16, 16, 16, __nv_bfloat16, wmma::row_major> ah[2], al[2];
            wmma::fragment<wmma::matrix_b, 16, 16, 16, __nv_bfloat16, wmma::row_major> bh[2], bl[2];
            #pragma unroll
            for (int r2 = 0; r2 < 2; r2++) {
                wmma::load_matrix_sync(ah[r2], &Ahi[(wm * 32 + r2 * 16) * ALD + ks * 16], ALD);
                wmma::load_matrix_sync(al[r2], &Alo[(wm * 32 + r2 * 16) * ALD + ks * 16], ALD);
            }
            #pragma unroll
            for (int cn = 0; cn < 2; cn++) {
                wmma::load_matrix_sync(bh[cn], &Bhi[(ks * 16) * BLD + wn * 32 + cn * 16], BLD);
                wmma::load_matrix_sync(bl[cn], &Blo[(ks * 16) * BLD + wn * 32 + cn * 16], BLD);
            }
            #pragma unroll
            for (int r2 = 0; r2 < 2; r2++)
                #pragma unroll
                for (int cn = 0; cn < 2; cn++) {
                    wmma::mma_sync(acc[r2][cn], ah[r2], bh[cn], acc[r2][cn]);
                    wmma::mma_sync(acc[r2][cn], ah[r2], bl[cn], acc[r2][cn]);
                    wmma::mma_sync(acc[r2][cn], al[r2], bh[cn], acc[r2][cn]);
                }
        }
        __syncthreads();
    }

    #pragma unroll
    for (int r2 = 0; r2 < 2; r2++)
        #pragma unroll
        for (int cn = 0; cn < 2; cn++)
            wmma::store_matrix_sync(&Csm[(wm * 32 + r2 * 16) * CLD + wn * 32 + cn * 16],
                                    acc[r2][cn], CLD, wmma::mem_row_major);
    __syncthreads();

    #pragma unroll
    for (int i = 0; i < 8; i++) {
        int idx = tid + i * 256;
        int row = idx >> 4;
        int c4  = (idx & 15) << 2;
        float4 v = *reinterpret_cast<const float4*>(&Csm[row * CLD + c4]);
        if (bias != nullptr) {
            float4 bv = *reinterpret_cast<const float4*>(bias + n0 + c4);
            v.x += bv.x; v.y += bv.y; v.z += bv.z; v.w += bv.w;
        }
        if (relu) {
            v.x = fmaxf(v.x, 0.f); v.y = fmaxf(v.y, 0.f);
            v.z = fmaxf(v.z, 0.f); v.w = fmaxf(v.w, 0.f);
        }
        *reinterpret_cast<float4*>(C + (long long)(m0 + row) * N + n0 + c4) = v;
    }
}

// ================== PV GEMM: o_att = beta @ h, fp16 2-term scheme ================
// beta in [0,1]: single fp16 (rel err <= 2^-11, convex-weighted in the sum).
// h: fp16 hi+lo split (~22-bit). acc += Af*Bhi; acc += Af*Blo  -> 2 mma/step.
// Same tile/structure as gemm_split_kernel (known-good 128x64, 8 warps).
static constexpr int PALD = GBK + 8;   // 40
static constexpr int PBLD = GBN + 8;   // 72
static constexpr int PV_SMEM_BYTES = 35840;  // Af(10240) + Bhi/Blo(4608*2) < Csm(34816)

__global__ void __launch_bounds__(256)
pv_f16_kernel(const float* __restrict__ beta, const float* __restrict__ h,
              float* __restrict__ oatt)
{
    __shared__ __align__(16) unsigned char smbuf[PV_SMEM_BYTES];
    __half* Af  = reinterpret_cast<__half*>(smbuf);
    __half* Bhi = Af + GBM * PALD;
    __half* Blo = Bhi + GBK * PBLD;
    float*  Csm = reinterpret_cast<float*>(smbuf);

    const float* A = beta + (long long)blockIdx.z * NTOK * NTOK;
    const float* B = h    + (long long)blockIdx.z * NTOK * CH;
    float*       C = oatt + (long long)blockIdx.z * NTOK * CH;
    const int m0  = blockIdx.y * GBM;
    const int n0  = blockIdx.x * GBN;
    const int tid = threadIdx.x;
    const int wid = tid >> 5;
    const int wm  = wid >> 1;  // 0..3
    const int wn  = wid & 1;   // 0..1

    wmma::fragment<wmma::accumulator, 16, 16, 16, float> acc[2][2];
    #pragma unroll
    for (int i = 0; i < 2; i++)
        #pragma unroll
        for (int j = 0; j < 2; j++)
            wmma::fill_fragment(acc[i][j], 0.0f);

    for (int kt = 0; kt < NTOK; kt += GBK) {
        #pragma unroll
        for (int i = 0; i < 4; i++) {
            int idx = tid + i * 256;
            int row = idx >> 3;
            int c4  = (idx & 7) << 2;
            float4 v = *reinterpret_cast<const float4*>(A + (long long)(m0 + row) * NTOK + kt + c4);
            cvt4h(v, &Af[row * PALD + c4]);
        }
        #pragma unroll
        for (int i = 0; i < 2; i++) {
            int idx = tid + i * 256;
            int row = idx >> 4;
            int c4  = (idx & 15) << 2;
            float4 v = *reinterpret_cast<const float4*>(B + (long long)(kt + row) * CH + n0 + c4);
            split4h(v, &Bhi[row * PBLD + c4], &Blo[row * PBLD + c4]);
        }
        __syncthreads();
        #pragma unroll
        for (int ks = 0; ks < 2; ks++) {
            wmma::fragment<wmma::matrix_a, 16, 16, 16, __half, wmma::row_major> af[2];
            wmma::fragment<wmma::matrix_b, 16, 16, 16, __half, wmma::row_major> bh[2], bl[2];
            #pragma unroll
            for (int r2 = 0; r2 < 2; r2++)
                wmma::load_matrix_sync(af[r2], &Af[(wm * 32 + r2 * 16) * PALD + ks * 16], PALD);
            #pragma unroll
            for (int cn = 0; cn < 2; cn++) {
                wmma::load_matrix_sync(bh[cn], &Bhi[(ks * 16) * PBLD + wn * 32 + cn * 16], PBLD);
                wmma::load_matrix_sync(bl[cn], &Blo[(ks * 16) * PBLD + wn * 32 + cn * 16], PBLD);
            }
            #pragma unroll
            for (int r2 = 0; r2 < 2; r2++)
                #pragma unroll
                for (int cn = 0; cn < 2; cn++) {
                    wmma::mma_sync(acc[r2][cn], af[r2], bh[cn], acc[r2][cn]);
                    wmma::mma_sync(acc[r2][cn], af[r2], bl[cn], acc[r2][cn]);
                }
        }
        __syncthreads();
    }

    #pragma unroll
    for (int r2 = 0; r2 < 2; r2++)
        #pragma unroll
        for (int cn = 0; cn < 2; cn++)
            wmma::store_matrix_sync(&Csm[(wm * 32 + r2 * 16) * CLD + wn * 32 + cn * 16],
                                    acc[r2][cn], CLD, wmma::mem_row_major);
    __syncthreads();

    #pragma unroll
    for (int i = 0; i < 8; i++) {
        int idx = tid + i * 256;
        int row = idx >> 4;
        int c4  = (idx & 15) << 2;
        float4 v = *reinterpret_cast<const float4*>(&Csm[row * CLD + c4]);
        *reinterpret_cast<float4*>(C + (long long)(m0 + row) * CH + n0 + c4) = v;
    }
}

// ================== scores: raw S = g @ f^T streamed out + online row max/sum ====
static constexpr int SLD = 132;
static constexpr int GLD = 72;
static constexpr int SCORES_SMEM = 4 * 128 * GLD * 2 + 128 * SLD * 4; // 141312 B

__global__ void __launch_bounds__(512)
scores_kernel(const float* __restrict__ g, const float* __restrict__ f,
              float* __restrict__ sraw, float* __restrict__ rowm, float* __restrict__ rowl)
{
    extern __shared__ unsigned char smraw[];
    __nv_bfloat16* Ghi = reinterpret_cast<__nv_bfloat16*>(smraw);
    __nv_bfloat16* Glo = Ghi + 128 * GLD;
    __nv_bfloat16* Fhi = Glo + 128 * GLD;
    __nv_bfloat16* Flo = Fhi + 128 * GLD;
    float*         S   = reinterpret_cast<float*>(Flo + 128 * GLD);

    const int b   = blockIdx.y;
    const int r0  = blockIdx.x * 128;
    const int tid = threadIdx.x;
    const int wid = tid >> 5;
    const int wm  = wid >> 2;
    const int wn  = wid & 3;

    const float* gbase = g + ((long long)b * NTOK + r0) * FGD;
    const float* fbase = f + (long long)b * NTOK * FGD;

    #pragma unroll
    for (int i = 0; i < 4; i++) {
        int idx = tid + i * 512;
        int row = idx >> 4;
        int c4  = (idx & 15) << 2;
        float4 v = *reinterpret_cast<const float4*>(gbase + row * FGD + c4);
        split4(v, &Ghi[row * GLD + c4], &Glo[row * GLD + c4]);
    }

    float m_run = -1e30f, l_run = 0.0f;
    const int srow = tid >> 2;
    const int q    = tid & 3;
    const float* Sscan = &S[srow * SLD + q * 32];

    for (int ci = 0; ci < 32; ci++) {
        __syncthreads();
        #pragma unroll
        for (int i = 0; i < 4; i++) {
            int idx = tid + i * 512;
            int row = idx >> 4;
            int c4  = (idx & 15) << 2;
            float4 v = *reinterpret_cast<const float4*>(fbase + (long long)(ci * 128 + row) * FGD + c4);
            split4(v, &Fhi[row * GLD + c4], &Flo[row * GLD + c4]);
        }
        __syncthreads();

        wmma::fragment<wmma::accumulator, 16, 16, 16, float> acc[2][2];
        #pragma unroll
        for (int i = 0; i < 2; i++)
            #pragma unroll
            for (int j = 0; j < 2; j++)
                wmma::fill_fragment(acc[i][j], 0.0f);

        #pragma unroll
        for (int ks = 0; ks < 4; ks++) {
            wmma::fragment<wmma::matrix_a, 16, 16, 16, __nv_bfloat16, wmma::row_major> ah[2], al[2];
            wmma::fragment<wmma::matrix_b, 16, 16, 16, __nv_bfloat16, wmma::col_major> bh[2], bl[2];
            #pragma unroll
            for (int r2 = 0; r2 < 2; r2++) {
                wmma::load_matrix_sync(ah[r2], &Ghi[(wm * 32 + r2 * 16) * GLD + ks * 16], GLD);
                wmma::load_matrix_sync(al[r2], &Glo[(wm * 32 + r2 * 16) * GLD + ks * 16], GLD);
            }
            #pragma unroll
            for (int cn = 0; cn < 2; cn++) {
                wmma::load_matrix_sync(bh[cn], &Fhi[(wn * 32 + cn * 16) * GLD + ks * 16], GLD);
                wmma::load_matrix_sync(bl[cn], &Flo[(wn * 32 + cn * 16) * GLD + ks * 16], GLD);
            }
            #pragma unroll
            for (int r2 = 0; r2 < 2; r2++)
                #pragma unroll
                for (int cn = 0; cn < 2; cn++) {
                    wmma::mma_sync(acc[r2][cn], ah[r2], bh[cn], acc[r2][cn]);
                    wmma::mma_sync(acc[r2][cn], ah[r2], bl[cn], acc[r2][cn]);
                    wmma::mma_sync(acc[r2][cn], al[r2], bh[cn], acc[r2][cn]);
                }
        }
        #pragma unroll
        for (int r2 = 0; r2 < 2; r2++)
            #pragma unroll
            for (int cn = 0; cn < 2; cn++)
                wmma::store_matrix_sync(&S[(wm * 32 + r2 * 16) * SLD + wn * 32 + cn * 16],
                                        acc[r2][cn], SLD, wmma::mem_row_major);
        __syncthreads();

        size_t gout = (size_t)(b * NTOK + r0) * NTOK + (size_t)ci * 128;
        #pragma unroll
        for (int i = 0; i < 8; i++) {
            int idx = tid + i * 512;
            int row = idx >> 5;
            int c4  = (idx & 31) << 2;
            float4 v = *reinterpret_cast<const float4*>(&S[row * SLD + c4]);
            *reinterpret_cast<float4*>(sraw + gout + (size_t)row * NTOK + c4) = v;
        }
        float vmax = -1e30f;
        #pragma unroll
        for (int j = 0; j < 32; j++) vmax = fmaxf(vmax, Sscan[j]);
        float mn = fmaxf(m_run, vmax);
        float add = 0.0f;
        #pragma unroll
        for (int j = 0; j < 32; j++) add += __expf(Sscan[j] - mn);
        l_run = l_run * __expf(m_run - mn) + add;
        m_run = mn;
    }

    #pragma unroll
    for (int off = 1; off < 4; off <<= 1) {
        float mo  = __shfl_xor_sync(0xffffffffu, m_run, off);
        float lo2 = __shfl_xor_sync(0xffffffffu, l_run, off);
        float mn  = fmaxf(m_run, mo);
        l_run = l_run * __expf(m_run - mn) + lo2 * __expf(mo - mn);
        m_run = mn;
    }
    if (q == 0) {
        rowm[b * NTOK + r0 + srow] = m_run;
        rowl[b * NTOK + r0 + srow] = l_run;
    }
}

// ================== normalize: beta = exp(s - m_row) / l_row =====================
__global__ void __launch_bounds__(256)
normalize_kernel(float* __restrict__ beta,
                 const float* __restrict__ rowm, const float* __restrict__ rowl)
{
    long long idx = (long long)blockIdx.x * 256 + threadIdx.x;
    if (idx >= (B_ELEMS >> 2)) return;
    int rowg = (int)(idx >> 10);
    float m   = __ldg(rowm + rowg);
    float inv = 1.0f / __ldg(rowl + rowg);
    float4 v = *reinterpret_cast<float4*>(beta + idx * 4);
    v.x = __expf(v.x - m) * inv;
    v.y = __expf(v.y - m) * inv;
    v.z = __expf(v.z - m) * inv;
    v.w = __expf(v.w - m) * inv;
    *reinterpret_cast<float4*>(beta + idx * 4) = v;
}

// ================== launch ========================================================
extern "C" void kernel_launch(void* const* d_in, const int* in_sizes, int n_in,
                              void* d_out, int out_size)
{
    (void)in_sizes; (void)n_in;
    const float* l  = (const float*)d_in[0];
    const float* r  = (const float*)d_in[1];
    const float* Wf = (const float*)d_in[2];
    const float* Wg = (const float*)d_in[3];
    const float* Wh = (const float*)d_in[4];
    const float* Wo = (const float*)d_in[5];
    const float* bf = (const float*)d_in[6];
    const float* bg = (const float*)d_in[7];
    const float* bh = (const float*)d_in[8];
    const float* bo = (const float*)d_in[9];
    float* out = (float*)d_out;

    float *p_f, *p_g, *p_h, *p_oatt, *p_rowm, *p_rowl, *p_bscr;
    cudaGetSymbolAddress((void**)&p_f,    d_f);
    cudaGetSymbolAddress((void**)&p_g,    d_g);
    cudaGetSymbolAddress((void**)&p_h,    d_h);
    cudaGetSymbolAddress((void**)&p_oatt, d_oatt);
    cudaGetSymbolAddress((void**)&p_rowm, d_rowm);
    cudaGetSymbolAddress((void**)&p_rowl, d_rowl);
    cudaGetSymbolAddress((void**)&p_bscr, d_beta_scratch);

    // output layout: reference returns (o, beta) -> o first, then beta
    float* o_out    = nullptr;
    float* beta_out = nullptr;
    long long osz = (long long)out_size;
    if (osz >= O_ELEMS + B_ELEMS) { o_out = out; beta_out = out + O_ELEMS; }
    else if (osz == B_ELEMS)      { beta_out = out; }
    else                          { o_out = out; beta_out = p_bscr; }

    cudaFuncSetAttribute(scores_kernel, cudaFuncAttributeMaxDynamicSharedMemorySize, SCORES_SMEM);

    // f = relu(l @ Wf + bf)   [16384, 64]
    gemm_split_kernel<<<dim3(1, 128, 1), 256>>>(l, Wf, bf, p_f, 512, 64, 0, 0, 0, 1);
    // g = relu(r @ Wg + bg)   [16384, 64]
    gemm_split_kernel<<<dim3(1, 128, 1), 256>>>(r, Wg, bg, p_g, 512, 64, 0, 0, 0, 1);
    // h = relu(l @ Wh + bh)   [16384, 512]
    gemm_split_kernel<<<dim3(8, 128, 1), 256>>>(l, Wh, bh, p_h, 512, 512, 0, 0, 0, 1);
    // raw scores + row max / sumexp
    scores_kernel<<<dim3(32, 4, 1), 512, SCORES_SMEM>>>(p_g, p_f, beta_out, p_rowm, p_rowl);
    // beta = softmax(s)
    normalize_kernel<<<65536, 256>>>(beta_out, p_rowm, p_rowl);
    if (o_out) {
        // o_att = beta @ h  (per batch) -- fp16 2-term PV
        pv_f16_kernel<<<dim3(8, 32, 4), 256>>>(beta_out, p_h, p_oatt);
        // o = relu(o_att @ Wo + bo)   [16384, 512]
        gemm_split_kernel<<<dim3(8, 128, 1), 256>>>(p_oatt, Wo, bo, o_out, 512, 512, 0, 0, 0, 1);
    }
}